// round 14
// baseline (speedup 1.0000x reference)
#include <cuda_runtime.h>
#include <cuda_fp16.h>

// TIME_WARPING: not-a-knot cubic spline fit + warped evaluation.
// R9 core (register IIR + shuffle halos, fp16x4 (y0,y1,M0,M1) packed
// intervals, stride-1 eval) + 4-row-per-CTA software pipeline with
// double-buffered packed coefficients: load latency of row r+1 hides
// behind eval of row r; one barrier per row.

#define S      4096
#define NT     256
#define CHUNK  16
#define W      6
#define RPC    4        // rows (channels) per CTA; same sample -> same scale

#define LAM     (-0.26794919243112270647f)
#define PL      ( 0.26794919243112270647f)
#define INV1ML2 ( 1.07735026918962576451f)

__device__ __forceinline__ int pswz(int i) { return i ^ ((i >> 4) & 15); }

__device__ __forceinline__ void pstore(uint2* spk, int i,
                                       float y0, float y1, float m0, float m1)
{
    __half2 hy = __floats2half2_rn(y0, y1);
    __half2 hm = __floats2half2_rn(m0, m1);
    uint2 v;
    v.x = *reinterpret_cast<unsigned*>(&hy);
    v.y = *reinterpret_cast<unsigned*>(&hm);
    spk[pswz(i)] = v;
}

// xa[m] = x[i0 - 7 + m], m in [0, 30).  y_{i0+k} = xa[7+k].
template<int MODE>
__device__ __forceinline__ void solve_and_pack(const float* xa, uint2* spk,
                                               int i0, float M1, float MS2)
{
    const float LP[6] = { 1.f, -0.26794919243112270647f, 0.07179676972449082073f,
                          -0.01923788646684063666f, 0.00515470534915383427f,
                          -0.00138119963856238452f };
    float pv[CHUNK];
    float p = 0.f, A = 0.f;

#define RR(m) (6.f * (xa[(m)] - 2.f * xa[(m) + 1] + xa[(m) + 2]))

    #pragma unroll
    for (int k = 0; k < CHUNK + 2 * W; ++k) {        // j = i0 - 6 + k
        float r;
        if (MODE == 1) {
            if (k <= 5)       r = -RR(14 - k);        // j<0: -r(2-j)
            else if (k == 6)  r = -(RR(8) - M1);      // j=0
            else if (k == 7)  r = 0.f;                // j=1: Dirichlet
            else if (k == 8)  r = RR(8) - M1;         // j=2
            else              r = RR(k);
        } else if (MODE == 2) {
            if (k == 19)      r = RR(19) - MS2;       // j = S-3
            else if (k == 20) r = 0.f;                // j = S-2
            else if (k == 21) r = -(RR(19) - MS2);    // j = S-1
            else if (k >= 22) r = -RR(46 - k);        // j>S-1
            else              r = RR(k);
        } else {
            r = RR(k);
        }
        if (k < CHUNK + W) {
            p = fmaf(LAM, p, r);
            if (k >= W) pv[k - W] = p;
        } else {
            A = fmaf(LP[k - (CHUNK + W)], r, A);
        }
    }
#undef RR

    float q      = fmaf(LAM, pv[CHUNK - 1], A) * INV1ML2;
    float u_next = PL * q;
    float u2     = 0.f;

    #pragma unroll
    for (int k = CHUNK - 1; k >= 0; --k) {
        q = fmaf(LAM, q, pv[k]);
        float u = PL * q;

        if (MODE == 1) {
            if (k == 2) u2 = u;
            if (k == 1) u = M1;
            if (k == 0) u = 2.f * M1 - u2;
        }
        if (MODE == 2) {
            if (k == 15) { u_next = 0.f; continue; }
            if (k == 14) { u_next = MS2; continue; }
            if (k == 13) {
                pstore(spk, i0 + 14, xa[21], xa[22], MS2, 2.f * MS2 - u);
            }
        }

        pstore(spk, i0 + k, xa[7 + k], xa[8 + k], u, u_next);
        u_next = u;
    }
}

struct RowRegs { float4 a0, a1, a2, a3; float h[7]; };

__device__ __forceinline__ void issue_loads(const float* __restrict__ xr,
                                            int i0, int lane, int tid, RowRegs& R)
{
    const float4* xv = (const float4*)(xr + i0);
    R.a0 = xv[0]; R.a1 = xv[1]; R.a2 = xv[2]; R.a3 = xv[3];
    if (lane == 0 && tid != 0) {
        #pragma unroll
        for (int q = 0; q < 7; ++q) R.h[q] = xr[i0 - 7 + q];
    } else if (lane == 31 && tid != NT - 1) {
        #pragma unroll
        for (int q = 0; q < 7; ++q) R.h[q] = xr[i0 + 16 + q];
    }
}

__device__ __forceinline__ void expand(const RowRegs& R, float* xa,
                                       int lane, int tid)
{
    xa[7]  = R.a0.x; xa[8]  = R.a0.y; xa[9]  = R.a0.z; xa[10] = R.a0.w;
    xa[11] = R.a1.x; xa[12] = R.a1.y; xa[13] = R.a1.z; xa[14] = R.a1.w;
    xa[15] = R.a2.x; xa[16] = R.a2.y; xa[17] = R.a2.z; xa[18] = R.a2.w;
    xa[19] = R.a3.x; xa[20] = R.a3.y; xa[21] = R.a3.z; xa[22] = R.a3.w;

    #pragma unroll
    for (int q = 0; q < 7; ++q)
        xa[q] = __shfl_up_sync(0xffffffffu, xa[16 + q], 1);
    #pragma unroll
    for (int q = 0; q < 7; ++q)
        xa[23 + q] = __shfl_down_sync(0xffffffffu, xa[7 + q], 1);

    if (lane == 0 && tid != 0) {
        #pragma unroll
        for (int q = 0; q < 7; ++q) xa[q] = R.h[q];
    }
    if (lane == 31 && tid != NT - 1) {
        #pragma unroll
        for (int q = 0; q < 7; ++q) xa[23 + q] = R.h[q];
    }
}

__global__ __launch_bounds__(NT)
void tw_kernel(const float* __restrict__ x,
               const float* __restrict__ scale,
               const int* __restrict__ mask,
               float* __restrict__ out, int C)
{
    extern __shared__ uint2 spk[];          // 2 * S entries (double buffer)

    const int cg   = blockIdx.x;            // channel group
    const int b    = blockIdx.y;
    const int tid  = threadIdx.x;
    const int lane = tid & 31;
    const size_t base = ((size_t)b * C + (size_t)cg * RPC) * (size_t)S;
    const float* xr   = x + base;
    float*       orow = out + base;

    if (mask[b] == 0) {                     // copy all RPC rows
        const float4* xi = (const float4*)xr;
        float4*       oo = (float4*)orow;
        #pragma unroll
        for (int g = 0; g < RPC * S / 4 / NT; ++g)
            oo[g * NT + tid] = xi[g * NT + tid];
        return;
    }

    const float scl = scale[b];
    const int   i0  = tid * CHUNK;

    RowRegs cur;
    issue_loads(xr, i0, lane, tid, cur);

    #pragma unroll
    for (int r = 0; r < RPC; ++r) {
        uint2* buf = spk + (r & 1) * S;
        const float* xrr = xr   + (size_t)r * S;
        float*       orr = orow + (size_t)r * S;

        float xa[30];
        expand(cur, xa, lane, tid);

        const float M1  = xa[7]  - 2.f * xa[8]  + xa[9];
        const float MS2 = xa[20] - 2.f * xa[21] + xa[22];

        if (tid == 0)            solve_and_pack<1>(xa, buf, i0, M1, MS2);
        else if (tid == NT - 1)  solve_and_pack<2>(xa, buf, i0, M1, MS2);
        else                     solve_and_pack<0>(xa, buf, i0, M1, MS2);

        __syncthreads();        // buf complete; safe vs prev eval via 2 buffers

        if (r + 1 < RPC)        // prefetch next row; latency hides behind eval
            issue_loads(xrr + S, i0, lane, tid, cur);

        // Warped cubic evaluation, stride-1 lane mapping; one LDS.64/elem.
        #pragma unroll
        for (int g = 0; g < S / NT; ++g) {
            const int v = g * NT + tid;
            float wv = fminf((float)v * scl, (float)(S - 1));
            int idx = (int)wv;
            if (idx > S - 2) idx = S - 2;
            float tt = wv - (float)idx;

            uint2 pk = buf[pswz(idx)];
            __half2 hy = *reinterpret_cast<__half2*>(&pk.x);
            __half2 hm = *reinterpret_cast<__half2*>(&pk.y);
            float2 yy = __half22float2(hy);
            float2 mm = __half22float2(hm);

            float bb = (yy.y - yy.x) - (2.f * mm.x + mm.y) * (1.f / 6.f);
            float cc = 0.5f * mm.x;
            float dd = (mm.y - mm.x) * (1.f / 6.f);
            orr[v] = fmaf(tt, fmaf(tt, fmaf(tt, dd, cc), bb), yy.x);
        }
    }
}

extern "C" void kernel_launch(void* const* d_in, const int* in_sizes, int n_in,
                              void* d_out, int out_size)
{
    const float* x     = (const float*)d_in[0];
    const float* scale = (const float*)d_in[1];
    const int*   mask  = (const int*)d_in[2];
    float*       out   = (float*)d_out;

    const int B = in_sizes[1];
    const int C = in_sizes[0] / (B * S);

    static bool attr_set = false;
    if (!attr_set) {
        cudaFuncSetAttribute(tw_kernel,
                             cudaFuncAttributeMaxDynamicSharedMemorySize,
                             2 * S * (int)sizeof(uint2));
        attr_set = true;
    }

    dim3 grid(C / RPC, B);
    tw_kernel<<<grid, NT, 2 * S * sizeof(uint2)>>>(x, scale, mask, out, C);
}